// round 9
// baseline (speedup 1.0000x reference)
#include <cuda_runtime.h>

#define Nn 8192
#define Cc 100
#define Dd 128
#define Hh 128
#define Oo 64
#define TPC 32                 // tokens per CTA chunk
#define NPAIR (TPC / 2)        // 16 token pairs
#define XSTRIDE 260            // words per pair-row: 260*4 = 1040 B, 16B-aligned rows
#define MAXW 356
#define NB 16
#define BT 512

// ---------------- packed f32x2 helpers ----------------
#define FMA2(d, a, b) asm("fma.rn.f32x2 %0, %1, %2, %0;" : "+l"(d) : "l"(a), "l"(b))
#define DUP2(d, s)    asm("mov.b64 %0, {%1, %1};" : "=l"(d) : "f"(s))
#define PK2(d, lo, hi) asm("mov.b64 %0, {%1, %2};" : "=l"(d) : "f"(lo), "f"(hi))
#define UNPK2(lo, hi, s) asm("mov.b64 {%0, %1}, %2;" : "=f"(lo), "=f"(hi) : "l"(s))

// ---------------- scratch (no allocations allowed) ----------------
__device__ int g_perm[Nn];
__device__ int g_workCat[MAXW];
__device__ int g_workStart[MAXW];
__device__ int g_workCnt[MAXW];
__device__ int g_numWork;

// ---------------- single-launch counting sort ----------------
__global__ void __launch_bounds__(BT) k_sort(const int* __restrict__ cat) {
    __shared__ int h_tot[128];
    __shared__ int h_pre[128];
    __shared__ int s_scan[128];
    int t = threadIdx.x, b = blockIdx.x;
    if (t < 128) { h_tot[t] = 0; h_pre[t] = 0; }
    __syncthreads();

    int myseg = b * BT;
    #pragma unroll 4
    for (int i = t; i < Nn; i += BT) {
        int c = cat[i];
        atomicAdd(&h_tot[c], 1);
        if (i < myseg) atomicAdd(&h_pre[c], 1);
    }
    __syncthreads();

    int p_mine = 0;
    if (t < 128) {
        int tot = (t < Cc) ? h_tot[t] : 0;
        p_mine = tot | (((tot + TPC - 1) / TPC) << 16);
        s_scan[t] = p_mine;
    }
    __syncthreads();
    #pragma unroll
    for (int d = 1; d < 128; d <<= 1) {
        int v = 0;
        if (t < 128 && t >= d) v = s_scan[t - d];
        __syncthreads();
        if (t < 128) s_scan[t] += v;
        __syncthreads();
    }

    if (t < Cc) {
        int excl = s_scan[t] - p_mine;
        int offEx = excl & 0xFFFF;
        h_pre[t] += offEx;
        if (b == 0) {
            int coffEx = excl >> 16;
            int tot = p_mine & 0xFFFF;
            int nch = p_mine >> 16;
            for (int j = 0; j < nch; j++) {
                g_workCat[coffEx + j]   = t;
                g_workStart[coffEx + j] = offEx + j * TPC;
                int rem = tot - j * TPC;
                g_workCnt[coffEx + j]   = rem < TPC ? rem : TPC;
            }
        }
    }
    if (b == 0 && t == 127) g_numWork = s_scan[127] >> 16;
    __syncthreads();

    int id = myseg + t;
    int pos = atomicAdd(&h_pre[cat[id]], 1);
    g_perm[pos] = id;
}

// ---------------- main fused MLP ----------------
// Weights streamed from L2 via prefetched LDG (no smem staging).
// SMEM = xp only (16.6KB). 3 CTAs/SM (reg-limited), single wave.
// Layer 1: warp = 16 pairs x 16 cols; lane = 2 pairs (lane&7) x 4 cols (lane>>3).
// Layer 2: warp = 8 pairs x 16 cols;  lane = 2 pairs x 2 cols.  h in xp in place.
__global__ void __launch_bounds__(256, 3)
k_mlp(const float* __restrict__ x,
      const float* __restrict__ W1, const float* __restrict__ b1,
      const float* __restrict__ W2, const float* __restrict__ b2,
      float* __restrict__ out) {
    extern __shared__ float sm[];
    float* xp = sm;                        // 16*260 f : pair-major packed x / h

    int w = blockIdx.x;
    if (w >= g_numWork) return;
    int c     = g_workCat[w];
    int start = g_workStart[w];
    int cnt   = g_workCnt[w];
    int t = threadIdx.x;

    // ---- stage x transposed+pair-packed: xp[p][d] = (x_{2p}[d], x_{2p+1}[d]) ----
    #pragma unroll
    for (int i = t; i < NPAIR * 32; i += 256) {
        int p = i >> 5, q = i & 31;            // q indexes d-quads
        int iA = 2 * p, iB = 2 * p + 1;
        int tA = (iA < cnt) ? g_perm[start + iA] : -1;
        int tB = (iB < cnt) ? g_perm[start + iB] : -1;
        float4 a = (tA >= 0) ? ((const float4*)(x + (size_t)tA * Dd))[q]
                             : make_float4(0.f, 0.f, 0.f, 0.f);
        float4 bb = (tB >= 0) ? ((const float4*)(x + (size_t)tB * Dd))[q]
                              : make_float4(0.f, 0.f, 0.f, 0.f);
        float* dst = xp + (size_t)p * XSTRIDE + 8 * q;
        ((float4*)dst)[0] = make_float4(a.x, bb.x, a.y, bb.y);
        ((float4*)dst)[1] = make_float4(a.z, bb.z, a.w, bb.w);
    }
    __syncthreads();

    int warp = t >> 5, lane = t & 31;

    // ================= layer 1 =================
    int lp = lane & 7;                     // pair group -> pairs 2lp, 2lp+1
    int cq = lane >> 3;                    // col quad within warp
    int cbase = 16 * warp + 4 * cq;        // lane's 4 H-cols
    int p0 = 2 * lp;

    unsigned long long acc[2][4];
    #pragma unroll
    for (int pp = 0; pp < 2; pp++)
        #pragma unroll
        for (int jj = 0; jj < 4; jj++) acc[pp][jj] = 0ULL;

    {
        const float* Wp = W1 + (size_t)c * Dd * Hh + cbase;
        float4 wa = *(const float4*)(Wp);
        float4 wb = *(const float4*)(Wp + Hh);
        #pragma unroll 2
        for (int d = 0; d < Dd; d += 2) {
            float4 na, nb;
            if (d + 2 < Dd) {
                na = *(const float4*)(Wp + (size_t)(d + 2) * Hh);
                nb = *(const float4*)(Wp + (size_t)(d + 3) * Hh);
            }
            ulonglong2 xv0 = *(const ulonglong2*)(xp + (size_t)(p0 + 0) * XSTRIDE + 2 * d);
            ulonglong2 xv1 = *(const ulonglong2*)(xp + (size_t)(p0 + 1) * XSTRIDE + 2 * d);
            unsigned long long a0, a1, a2w, a3, b0, b1, b2w, b3;
            DUP2(a0, wa.x); DUP2(a1, wa.y); DUP2(a2w, wa.z); DUP2(a3, wa.w);
            DUP2(b0, wb.x); DUP2(b1, wb.y); DUP2(b2w, wb.z); DUP2(b3, wb.w);
            FMA2(acc[0][0], xv0.x, a0); FMA2(acc[0][1], xv0.x, a1);
            FMA2(acc[0][2], xv0.x, a2w); FMA2(acc[0][3], xv0.x, a3);
            FMA2(acc[1][0], xv1.x, a0); FMA2(acc[1][1], xv1.x, a1);
            FMA2(acc[1][2], xv1.x, a2w); FMA2(acc[1][3], xv1.x, a3);
            FMA2(acc[0][0], xv0.y, b0); FMA2(acc[0][1], xv0.y, b1);
            FMA2(acc[0][2], xv0.y, b2w); FMA2(acc[0][3], xv0.y, b3);
            FMA2(acc[1][0], xv1.y, b0); FMA2(acc[1][1], xv1.y, b1);
            FMA2(acc[1][2], xv1.y, b2w); FMA2(acc[1][3], xv1.y, b3);
            wa = na; wb = nb;
        }
    }

    __syncthreads();   // all warps done reading xp before h overwrites it

    // epilogue 1: bias + relu, store pair-packed h in place over xp
    {
        float4 bv = *(const float4*)(b1 + (size_t)c * Hh + cbase);
        float bj[4] = {bv.x, bv.y, bv.z, bv.w};
        #pragma unroll
        for (int pp = 0; pp < 2; pp++) {
            ulonglong2 v;
            float l0, h0, l1, h1, l2, h2, l3, h3;
            UNPK2(l0, h0, acc[pp][0]);
            UNPK2(l1, h1, acc[pp][1]);
            UNPK2(l2, h2, acc[pp][2]);
            UNPK2(l3, h3, acc[pp][3]);
            l0 = fmaxf(l0 + bj[0], 0.f); h0 = fmaxf(h0 + bj[0], 0.f);
            l1 = fmaxf(l1 + bj[1], 0.f); h1 = fmaxf(h1 + bj[1], 0.f);
            PK2(v.x, l0, h0); PK2(v.y, l1, h1);
            *(ulonglong2*)(xp + (size_t)(p0 + pp) * XSTRIDE + 2 * cbase) = v;
            l2 = fmaxf(l2 + bj[2], 0.f); h2 = fmaxf(h2 + bj[2], 0.f);
            l3 = fmaxf(l3 + bj[3], 0.f); h3 = fmaxf(h3 + bj[3], 0.f);
            PK2(v.x, l2, h2); PK2(v.y, l3, h3);
            *(ulonglong2*)(xp + (size_t)(p0 + pp) * XSTRIDE + 2 * cbase + 4) = v;
        }
    }

    __syncthreads();   // h complete before layer 2 reads

    // ================= layer 2 =================
    int pg = warp & 1;                     // pair group (8 pairs)
    int cg = warp >> 1;                    // col group
    int q0 = 8 * pg + 2 * (lane & 3);      // lane's 2 pairs
    int cb2 = 16 * cg + 2 * (lane >> 2);   // lane's 2 O-cols

    unsigned long long acc2[2][2];
    acc2[0][0] = acc2[0][1] = acc2[1][0] = acc2[1][1] = 0ULL;

    {
        const float* W2p = W2 + (size_t)c * Hh * Oo + cb2;
        float2 wA = *(const float2*)(W2p);
        float2 wB = *(const float2*)(W2p + Oo);
        #pragma unroll 2
        for (int k = 0; k < Hh; k += 2) {
            float2 nA, nB;
            if (k + 2 < Hh) {
                nA = *(const float2*)(W2p + (size_t)(k + 2) * Oo);
                nB = *(const float2*)(W2p + (size_t)(k + 3) * Oo);
            }
            ulonglong2 h0 = *(const ulonglong2*)(xp + (size_t)(q0 + 0) * XSTRIDE + 2 * k);
            ulonglong2 h1 = *(const ulonglong2*)(xp + (size_t)(q0 + 1) * XSTRIDE + 2 * k);
            unsigned long long wA0, wA1, wB0, wB1;
            DUP2(wA0, wA.x); DUP2(wA1, wA.y);
            DUP2(wB0, wB.x); DUP2(wB1, wB.y);
            FMA2(acc2[0][0], h0.x, wA0); FMA2(acc2[0][1], h0.x, wA1);
            FMA2(acc2[1][0], h1.x, wA0); FMA2(acc2[1][1], h1.x, wA1);
            FMA2(acc2[0][0], h0.y, wB0); FMA2(acc2[0][1], h0.y, wB1);
            FMA2(acc2[1][0], h1.y, wB0); FMA2(acc2[1][1], h1.y, wB1);
            wA = nA; wB = nB;
        }
    }

    // epilogue 2: bias + store (unpack token pairs)
    {
        float2 b2v = *(const float2*)(b2 + (size_t)c * Oo + cb2);
        #pragma unroll
        for (int pp = 0; pp < 2; pp++) {
            int iA = 2 * (q0 + pp), iB = iA + 1;
            int tA = (iA < cnt) ? g_perm[start + iA] : -1;
            int tB = (iB < cnt) ? g_perm[start + iB] : -1;
            float l0, h0, l1, h1;
            UNPK2(l0, h0, acc2[pp][0]);
            UNPK2(l1, h1, acc2[pp][1]);
            if (tA >= 0) {
                float2 o; o.x = l0 + b2v.x; o.y = l1 + b2v.y;
                *(float2*)(out + (size_t)tA * Oo + cb2) = o;
            }
            if (tB >= 0) {
                float2 o; o.x = h0 + b2v.x; o.y = h1 + b2v.y;
                *(float2*)(out + (size_t)tB * Oo + cb2) = o;
            }
        }
    }
}

extern "C" void kernel_launch(void* const* d_in, const int* in_sizes, int n_in,
                              void* d_out, int out_size) {
    const float* x   = (const float*)d_in[0];
    const int*   cat = (const int*)  d_in[1];
    const float* W1  = (const float*)d_in[2];
    const float* b1  = (const float*)d_in[3];
    const float* W2  = (const float*)d_in[4];
    const float* b2  = (const float*)d_in[5];
    float* out = (float*)d_out;

    size_t smem = (size_t)(NPAIR * XSTRIDE) * sizeof(float);   // 16640 B
    static bool attr_set = false;
    if (!attr_set) {
        cudaFuncSetAttribute(k_mlp, cudaFuncAttributeMaxDynamicSharedMemorySize, (int)smem);
        attr_set = true;
    }

    k_sort<<<NB, BT>>>(cat);
    k_mlp<<<MAXW, 256, smem>>>(x, W1, b1, W2, b2, out);
}

// round 10
// speedup vs baseline: 1.6791x; 1.6791x over previous
#include <cuda_runtime.h>

#define Nn 8192
#define Cc 100
#define Dd 128
#define Hh 128
#define Oo 64
#define TPC 32                 // tokens per CTA chunk
#define NPAIR (TPC / 2)        // 16 token pairs
#define XSTRIDE 260            // words per pair-row (1040 B: 16B-aligned, bank-spread)
#define MAXW 356
#define NB 16
#define BT 512

// ---------------- packed f32x2 helpers ----------------
#define FMA2(d, a, b) asm("fma.rn.f32x2 %0, %1, %2, %0;" : "+l"(d) : "l"(a), "l"(b))
#define DUP2(d, s)    asm("mov.b64 %0, {%1, %1};" : "=l"(d) : "f"(s))
#define PK2(d, lo, hi) asm("mov.b64 %0, {%1, %2};" : "=l"(d) : "f"(lo), "f"(hi))
#define UNPK2(lo, hi, s) asm("mov.b64 {%0, %1}, %2;" : "=f"(lo), "=f"(hi) : "l"(s))
#define CP_ASYNC16(smem_u32, gptr) \
    asm volatile("cp.async.cg.shared.global [%0], [%1], 16;" :: "r"(smem_u32), "l"(gptr))
#define CP_ASYNC_COMMIT() asm volatile("cp.async.commit_group;")
#define CP_ASYNC_WAIT0()  asm volatile("cp.async.wait_group 0;")

// ---------------- scratch (no allocations allowed) ----------------
__device__ int g_perm[Nn];
__device__ int g_workCat[MAXW];
__device__ int g_workStart[MAXW];
__device__ int g_workCnt[MAXW];
__device__ int g_numWork;

// ---------------- single-launch counting sort ----------------
__global__ void __launch_bounds__(BT) k_sort(const int* __restrict__ cat) {
    __shared__ int h_tot[128];
    __shared__ int h_pre[128];
    __shared__ int s_scan[128];
    int t = threadIdx.x, b = blockIdx.x;
    if (t < 128) { h_tot[t] = 0; h_pre[t] = 0; }
    __syncthreads();

    int myseg = b * BT;
    #pragma unroll 4
    for (int i = t; i < Nn; i += BT) {
        int c = cat[i];
        atomicAdd(&h_tot[c], 1);
        if (i < myseg) atomicAdd(&h_pre[c], 1);
    }
    __syncthreads();

    int p_mine = 0;
    if (t < 128) {
        int tot = (t < Cc) ? h_tot[t] : 0;
        p_mine = tot | (((tot + TPC - 1) / TPC) << 16);
        s_scan[t] = p_mine;
    }
    __syncthreads();
    #pragma unroll
    for (int d = 1; d < 128; d <<= 1) {
        int v = 0;
        if (t < 128 && t >= d) v = s_scan[t - d];
        __syncthreads();
        if (t < 128) s_scan[t] += v;
        __syncthreads();
    }

    if (t < Cc) {
        int excl = s_scan[t] - p_mine;
        int offEx = excl & 0xFFFF;
        h_pre[t] += offEx;
        if (b == 0) {
            int coffEx = excl >> 16;
            int tot = p_mine & 0xFFFF;
            int nch = p_mine >> 16;
            for (int j = 0; j < nch; j++) {
                g_workCat[coffEx + j]   = t;
                g_workStart[coffEx + j] = offEx + j * TPC;
                int rem = tot - j * TPC;
                g_workCnt[coffEx + j]   = rem < TPC ? rem : TPC;
            }
        }
    }
    if (b == 0 && t == 127) g_numWork = s_scan[127] >> 16;
    __syncthreads();

    int id = myseg + t;
    int pos = atomicAdd(&h_pre[cat[id]], 1);
    g_perm[pos] = id;
}

// ---------------- main fused MLP (round-7 layout + SW pipelining + cp.async) ----------
// Layer 1: warp = 8 pairs x 32 cols; lane = 2 pairs x 4 cols.
// Layer 2: warp = 8 pairs x 16 cols; lane = 2 pairs x 2 cols.
// SMEM = W1 64KB + W2 32KB + xp 16.6KB -> 2 CTAs/SM. h overwrites xp in place.
__global__ void __launch_bounds__(256, 2)
k_mlp(const float* __restrict__ x,
      const float* __restrict__ W1, const float* __restrict__ b1,
      const float* __restrict__ W2, const float* __restrict__ b2,
      float* __restrict__ out) {
    extern __shared__ float sm[];
    float* W1s = sm;                      // 16384 f (64KB)  [d][h]
    float* W2s = W1s + Dd * Hh;           // 8192 f  (32KB)  [k][o]
    float* xp  = W2s + Hh * Oo;           // 16*260 f : pair-major packed x / h

    int w = blockIdx.x;
    if (w >= g_numWork) return;
    int c     = g_workCat[w];
    int start = g_workStart[w];
    int cnt   = g_workCnt[w];
    int t = threadIdx.x;

    // ---- stage weights via cp.async (fire-and-forget; overlaps x gather) ----
    {
        unsigned w1a = (unsigned)__cvta_generic_to_shared(W1s);
        unsigned w2a = (unsigned)__cvta_generic_to_shared(W2s);
        const float4* W1g = (const float4*)(W1 + (size_t)c * Dd * Hh);
        const float4* W2g = (const float4*)(W2 + (size_t)c * Hh * Oo);
        #pragma unroll
        for (int i = t; i < Dd * Hh / 4; i += 256)
            CP_ASYNC16(w1a + i * 16, W1g + i);
        #pragma unroll
        for (int i = t; i < Hh * Oo / 4; i += 256)
            CP_ASYNC16(w2a + i * 16, W2g + i);
        CP_ASYNC_COMMIT();
    }

    // ---- stage x transposed+pair-packed: xp[p][d] = (x_{2p}[d], x_{2p+1}[d]) ----
    #pragma unroll
    for (int i = t; i < NPAIR * 32; i += 256) {
        int p = i >> 5, q = i & 31;            // q indexes d-quads
        int iA = 2 * p, iB = 2 * p + 1;
        int tA = (iA < cnt) ? g_perm[start + iA] : -1;
        int tB = (iB < cnt) ? g_perm[start + iB] : -1;
        float4 a = (tA >= 0) ? ((const float4*)(x + (size_t)tA * Dd))[q]
                             : make_float4(0.f, 0.f, 0.f, 0.f);
        float4 bb = (tB >= 0) ? ((const float4*)(x + (size_t)tB * Dd))[q]
                              : make_float4(0.f, 0.f, 0.f, 0.f);
        float* dst = xp + (size_t)p * XSTRIDE + 8 * q;
        ((float4*)dst)[0] = make_float4(a.x, bb.x, a.y, bb.y);
        ((float4*)dst)[1] = make_float4(a.z, bb.z, a.w, bb.w);
    }
    CP_ASYNC_WAIT0();
    __syncthreads();

    int warp = t >> 5, lane = t & 31;
    int pg = warp & 1;                     // pair group (8 pairs)
    int cg = warp >> 1;                    // col group
    int p0 = 8 * pg + 2 * (lane & 3);      // lane's 2 pairs
    int cbase = 32 * cg + 4 * (lane >> 2); // lane's 4 cols (layer 1)

    // ---- layer 1: software-pipelined; acc[pair][col] = 8 packed accumulators ----
    unsigned long long acc[2][4];
    #pragma unroll
    for (int pp = 0; pp < 2; pp++)
        #pragma unroll
        for (int jj = 0; jj < 4; jj++) acc[pp][jj] = 0ULL;

    {
        const float* xr0 = xp + (size_t)(p0 + 0) * XSTRIDE;
        const float* xr1 = xp + (size_t)(p0 + 1) * XSTRIDE;
        const float* Wr  = W1s + cbase;
        ulonglong2 xv0 = *(const ulonglong2*)(xr0);
        ulonglong2 xv1 = *(const ulonglong2*)(xr1);
        float4 wa = *(const float4*)(Wr);
        float4 wb = *(const float4*)(Wr + Hh);
        #pragma unroll 4
        for (int d = 0; d < Dd; d += 2) {
            ulonglong2 nx0, nx1;
            float4 nwa, nwb;
            if (d + 2 < Dd) {
                nx0 = *(const ulonglong2*)(xr0 + 2 * (d + 2));
                nx1 = *(const ulonglong2*)(xr1 + 2 * (d + 2));
                nwa = *(const float4*)(Wr + (size_t)(d + 2) * Hh);
                nwb = *(const float4*)(Wr + (size_t)(d + 3) * Hh);
            }
            unsigned long long a0, a1, a2w, a3, b0, b1, b2w, b3;
            DUP2(a0, wa.x); DUP2(a1, wa.y); DUP2(a2w, wa.z); DUP2(a3, wa.w);
            DUP2(b0, wb.x); DUP2(b1, wb.y); DUP2(b2w, wb.z); DUP2(b3, wb.w);
            FMA2(acc[0][0], xv0.x, a0); FMA2(acc[0][1], xv0.x, a1);
            FMA2(acc[0][2], xv0.x, a2w); FMA2(acc[0][3], xv0.x, a3);
            FMA2(acc[1][0], xv1.x, a0); FMA2(acc[1][1], xv1.x, a1);
            FMA2(acc[1][2], xv1.x, a2w); FMA2(acc[1][3], xv1.x, a3);
            FMA2(acc[0][0], xv0.y, b0); FMA2(acc[0][1], xv0.y, b1);
            FMA2(acc[0][2], xv0.y, b2w); FMA2(acc[0][3], xv0.y, b3);
            FMA2(acc[1][0], xv1.y, b0); FMA2(acc[1][1], xv1.y, b1);
            FMA2(acc[1][2], xv1.y, b2w); FMA2(acc[1][3], xv1.y, b3);
            xv0 = nx0; xv1 = nx1; wa = nwa; wb = nwb;
        }
    }

    __syncthreads();   // all warps done reading xp before h overwrites it

    // epilogue 1: bias + relu, store pair-packed h in place over xp
    {
        float4 bv = *(const float4*)(b1 + (size_t)c * Hh + cbase);
        float bj[4] = {bv.x, bv.y, bv.z, bv.w};
        #pragma unroll
        for (int pp = 0; pp < 2; pp++) {
            ulonglong2 v;
            float l0, h0, l1, h1, l2, h2, l3, h3;
            UNPK2(l0, h0, acc[pp][0]);
            UNPK2(l1, h1, acc[pp][1]);
            UNPK2(l2, h2, acc[pp][2]);
            UNPK2(l3, h3, acc[pp][3]);
            l0 = fmaxf(l0 + bj[0], 0.f); h0 = fmaxf(h0 + bj[0], 0.f);
            l1 = fmaxf(l1 + bj[1], 0.f); h1 = fmaxf(h1 + bj[1], 0.f);
            PK2(v.x, l0, h0); PK2(v.y, l1, h1);
            *(ulonglong2*)(xp + (size_t)(p0 + pp) * XSTRIDE + 2 * cbase) = v;
            l2 = fmaxf(l2 + bj[2], 0.f); h2 = fmaxf(h2 + bj[2], 0.f);
            l3 = fmaxf(l3 + bj[3], 0.f); h3 = fmaxf(h3 + bj[3], 0.f);
            PK2(v.x, l2, h2); PK2(v.y, l3, h3);
            *(ulonglong2*)(xp + (size_t)(p0 + pp) * XSTRIDE + 2 * cbase + 4) = v;
        }
    }

    __syncthreads();   // h complete before layer 2 reads

    // ---- layer 2: software-pipelined; acc2[pair][col] = 4 packed accumulators ----
    int cb2 = 16 * cg + 2 * (lane >> 2);   // lane's 2 cols (layer 2)
    unsigned long long acc2[2][2];
    acc2[0][0] = acc2[0][1] = acc2[1][0] = acc2[1][1] = 0ULL;

    {
        const float* hr0 = xp + (size_t)(p0 + 0) * XSTRIDE;
        const float* hr1 = xp + (size_t)(p0 + 1) * XSTRIDE;
        const float* Wr2 = W2s + cb2;
        ulonglong2 h0 = *(const ulonglong2*)(hr0);
        ulonglong2 h1 = *(const ulonglong2*)(hr1);
        float2 wA = *(const float2*)(Wr2);
        float2 wB = *(const float2*)(Wr2 + Oo);
        #pragma unroll 4
        for (int k = 0; k < Hh; k += 2) {
            ulonglong2 nh0, nh1;
            float2 nA, nB;
            if (k + 2 < Hh) {
                nh0 = *(const ulonglong2*)(hr0 + 2 * (k + 2));
                nh1 = *(const ulonglong2*)(hr1 + 2 * (k + 2));
                nA = *(const float2*)(Wr2 + (size_t)(k + 2) * Oo);
                nB = *(const float2*)(Wr2 + (size_t)(k + 3) * Oo);
            }
            unsigned long long wA0, wA1, wB0, wB1;
            DUP2(wA0, wA.x); DUP2(wA1, wA.y);
            DUP2(wB0, wB.x); DUP2(wB1, wB.y);
            FMA2(acc2[0][0], h0.x, wA0); FMA2(acc2[0][1], h0.x, wA1);
            FMA2(acc2[1][0], h1.x, wA0); FMA2(acc2[1][1], h1.x, wA1);
            FMA2(acc2[0][0], h0.y, wB0); FMA2(acc2[0][1], h0.y, wB1);
            FMA2(acc2[1][0], h1.y, wB0); FMA2(acc2[1][1], h1.y, wB1);
            h0 = nh0; h1 = nh1; wA = nA; wB = nB;
        }
    }

    // epilogue 2: bias + store (unpack token pairs)
    {
        float2 b2v = *(const float2*)(b2 + (size_t)c * Oo + cb2);
        #pragma unroll
        for (int pp = 0; pp < 2; pp++) {
            int iA = 2 * (p0 + pp), iB = iA + 1;
            int tA = (iA < cnt) ? g_perm[start + iA] : -1;
            int tB = (iB < cnt) ? g_perm[start + iB] : -1;
            float l0, h0, l1, h1;
            UNPK2(l0, h0, acc2[pp][0]);
            UNPK2(l1, h1, acc2[pp][1]);
            if (tA >= 0) {
                float2 o; o.x = l0 + b2v.x; o.y = l1 + b2v.y;
                *(float2*)(out + (size_t)tA * Oo + cb2) = o;
            }
            if (tB >= 0) {
                float2 o; o.x = h0 + b2v.x; o.y = h1 + b2v.y;
                *(float2*)(out + (size_t)tB * Oo + cb2) = o;
            }
        }
    }
}

extern "C" void kernel_launch(void* const* d_in, const int* in_sizes, int n_in,
                              void* d_out, int out_size) {
    const float* x   = (const float*)d_in[0];
    const int*   cat = (const int*)  d_in[1];
    const float* W1  = (const float*)d_in[2];
    const float* b1  = (const float*)d_in[3];
    const float* W2  = (const float*)d_in[4];
    const float* b2  = (const float*)d_in[5];
    float* out = (float*)d_out;

    size_t smem = (size_t)(Dd * Hh + Hh * Oo + NPAIR * XSTRIDE) * sizeof(float); // 114944 B
    static bool attr_set = false;
    if (!attr_set) {
        cudaFuncSetAttribute(k_mlp, cudaFuncAttributeMaxDynamicSharedMemorySize, (int)smem);
        attr_set = true;
    }

    k_sort<<<NB, BT>>>(cat);
    k_mlp<<<MAXW, 256, smem>>>(x, W1, b1, W2, b2, out);
}